// round 4
// baseline (speedup 1.0000x reference)
#include <cuda_runtime.h>
#include <cuda_fp16.h>
#include <math.h>

#define NN 100000
#define EE 3200000
#define NF 256
#define NH 128
#define NC 16
#define SCAN_NBLK ((NN + 1023) / 1024)
#define P1_WARPS 4736   // 592 blocks * 8 warps

// ---- static device scratch ----
__device__ unsigned long long g_degcnt[NN];   // hi32: count, lo32: deg*2^20
__device__ float   g_dinv[NN];
__device__ int     g_start[NN + 1];
__device__ int     g_cursor[NN];
__device__ int     g_bsum[256];
__device__ unsigned long long g_edge[EE];     // hi32: src, lo32: float bits of norm
__device__ __half2 g_xw1h[(size_t)NN * (NH / 2)];
__device__ float   g_hw2[(size_t)NN * NC];

// ---------------------------------------------------------------- init
__global__ void k_init() {
    int i = blockIdx.x * blockDim.x + threadIdx.x;
    if (i < NN) g_degcnt[i] = (1ULL << 20);   // deg=1.0 (self-loop), cnt=0
}

// ------------------------------------------ degree + count (one packed atomic)
__global__ void k_deg(const int* __restrict__ ei, const float* __restrict__ ew) {
    int e = blockIdx.x * blockDim.x + threadIdx.x;
    if (e < EE) {
        int c = ei[EE + e];
        unsigned fw = (unsigned)__float2uint_rn(ew[e] * 1048576.0f);
        atomicAdd(&g_degcnt[c], (1ULL << 32) | (unsigned long long)fw);
    }
}

// ------------------------------------------ 3-phase scan (+ dinv in phase 1)
__global__ void __launch_bounds__(1024) k_scan1() {
    __shared__ int wsum[32];
    int t = threadIdx.x, lane = t & 31, warp = t >> 5;
    int i = blockIdx.x * 1024 + t;
    int v = 0;
    if (i < NN) {
        unsigned long long pk = g_degcnt[i];
        v = (int)(pk >> 32);
        float deg = (float)(unsigned)(pk & 0xffffffffULL) * (1.0f / 1048576.0f);
        g_dinv[i] = rsqrtf(deg);              // deg >= 1 always
    }
    int x = v;
    #pragma unroll
    for (int off = 1; off < 32; off <<= 1) {
        int y = __shfl_up_sync(0xffffffffu, x, off);
        if (lane >= off) x += y;
    }
    if (lane == 31) wsum[warp] = x;
    __syncthreads();
    if (warp == 0) {
        int s = wsum[lane];
        #pragma unroll
        for (int off = 1; off < 32; off <<= 1) {
            int y = __shfl_up_sync(0xffffffffu, s, off);
            if (lane >= off) s += y;
        }
        wsum[lane] = s;
    }
    __syncthreads();
    int incl = x + (warp > 0 ? wsum[warp - 1] : 0);
    if (i < NN) g_start[i] = incl - v;
    if (t == 1023) g_bsum[blockIdx.x] = incl;
}

__global__ void k_scan2() {
    int t = threadIdx.x, lane = t & 31, warp = t >> 5;
    __shared__ int wsum[4];
    int v = (t < SCAN_NBLK) ? g_bsum[t] : 0;
    int x = v;
    #pragma unroll
    for (int off = 1; off < 32; off <<= 1) {
        int y = __shfl_up_sync(0xffffffffu, x, off);
        if (lane >= off) x += y;
    }
    if (lane == 31) wsum[warp] = x;
    __syncthreads();
    int woff = 0;
    for (int w = 0; w < warp; w++) woff += wsum[w];
    int incl = x + woff;
    if (t < SCAN_NBLK) g_bsum[t] = incl - v;
    if (t == SCAN_NBLK - 1) g_start[NN] = incl;
}

__global__ void __launch_bounds__(1024) k_scan3() {
    int i = blockIdx.x * 1024 + threadIdx.x;
    if (i < NN) {
        int s = g_start[i] + g_bsum[blockIdx.x];
        g_start[i]  = s;
        g_cursor[i] = s;
    }
}

// ------------------------------------- scatter edges into CSC, packed records
__global__ void k_scatter(const int* __restrict__ ei, const float* __restrict__ ew) {
    int e = blockIdx.x * blockDim.x + threadIdx.x;
    if (e < EE) {
        int r = ei[e];
        int c = ei[EE + e];
        float nrm = g_dinv[r] * ew[e] * g_dinv[c];
        int pos = atomicAdd(&g_cursor[c], 1);
        g_edge[pos] = ((unsigned long long)(unsigned)r << 32)
                    | (unsigned long long)__float_as_uint(nrm);
    }
}

// ------------------------------------------------------------- GEMM1: X@W1
// Tensor-core HMMA: BM=128, BN=128(full), BK=32, 8 warps (4M x 2N), fp32 accum.
__global__ void __launch_bounds__(256) k_gemm1(const float* __restrict__ A,
                                               const float* __restrict__ B) {
    __shared__ __half sA[128 * 40];   // 128 rows x 32 k (+8 pad)
    __shared__ __half sB[32 * 136];   // 32 k-rows x 128 n (+8 pad)

    const int tid  = threadIdx.x;
    const int lane = tid & 31;
    const int w    = tid >> 5;
    const int wm   = (w & 3) * 32;
    const int wn   = (w >> 2) * 64;
    const int m0   = blockIdx.x * 128;
    const int g    = lane >> 2;
    const int tg   = lane & 3;

    float acc[2][8][4];
    #pragma unroll
    for (int mt = 0; mt < 2; mt++)
        #pragma unroll
        for (int nt = 0; nt < 8; nt++)
            #pragma unroll
            for (int j = 0; j < 4; j++) acc[mt][nt][j] = 0.0f;

    // A-tile load coords: 2 threads per row, 16 floats each
    const int ar = tid >> 1;
    const int ac = (tid & 1) * 16;
    // B-tile load coords: 8 threads per k-row, 16 floats each
    const int bk = tid >> 3;
    const int bs = (tid & 7) * 16;

    float4 va[4], vb[4];
    {   // prefetch ks=0
        int gr = m0 + ar;
        #pragma unroll
        for (int j = 0; j < 4; j++)
            va[j] = (gr < NN) ? *(const float4*)(A + (size_t)gr * NF + ac + j * 4)
                              : make_float4(0.f, 0.f, 0.f, 0.f);
        #pragma unroll
        for (int j = 0; j < 4; j++)
            vb[j] = *(const float4*)(B + (size_t)bk * NH + bs + j * 4);
    }

    for (int ks = 0; ks < 8; ks++) {
        __syncthreads();
        {   // store tiles
            __half2 ha[8];
            #pragma unroll
            for (int j = 0; j < 4; j++) {
                ha[j * 2]     = __floats2half2_rn(va[j].x, va[j].y);
                ha[j * 2 + 1] = __floats2half2_rn(va[j].z, va[j].w);
            }
            *(uint4*)&sA[ar * 40 + ac]     = *(uint4*)&ha[0];
            *(uint4*)&sA[ar * 40 + ac + 8] = *(uint4*)&ha[4];
            __half2 hb[8];
            #pragma unroll
            for (int j = 0; j < 4; j++) {
                hb[j * 2]     = __floats2half2_rn(vb[j].x, vb[j].y);
                hb[j * 2 + 1] = __floats2half2_rn(vb[j].z, vb[j].w);
            }
            *(uint4*)&sB[bk * 136 + bs]     = *(uint4*)&hb[0];
            *(uint4*)&sB[bk * 136 + bs + 8] = *(uint4*)&hb[4];
        }
        __syncthreads();

        if (ks < 7) {   // prefetch next
            int k0n = (ks + 1) * 32;
            int gr = m0 + ar;
            #pragma unroll
            for (int j = 0; j < 4; j++)
                va[j] = (gr < NN) ? *(const float4*)(A + (size_t)gr * NF + k0n + ac + j * 4)
                                  : make_float4(0.f, 0.f, 0.f, 0.f);
            #pragma unroll
            for (int j = 0; j < 4; j++)
                vb[j] = *(const float4*)(B + (size_t)(k0n + bk) * NH + bs + j * 4);
        }

        #pragma unroll
        for (int o = 0; o < 32; o += 16) {
            unsigned a[2][4];
            #pragma unroll
            for (int mt = 0; mt < 2; mt++) {
                unsigned addr = (unsigned)__cvta_generic_to_shared(
                    &sA[(wm + mt * 16 + (lane & 15)) * 40 + o + ((lane >> 4) << 3)]);
                asm volatile("ldmatrix.sync.aligned.m8n8.x4.shared.b16 {%0,%1,%2,%3},[%4];"
                             : "=r"(a[mt][0]), "=r"(a[mt][1]), "=r"(a[mt][2]), "=r"(a[mt][3])
                             : "r"(addr));
            }
            #pragma unroll
            for (int nt = 0; nt < 8; nt++) {
                unsigned b[2];
                unsigned addr = (unsigned)__cvta_generic_to_shared(
                    &sB[(o + (lane & 15)) * 136 + wn + nt * 8]);
                asm volatile("ldmatrix.sync.aligned.m8n8.x2.trans.shared.b16 {%0,%1},[%2];"
                             : "=r"(b[0]), "=r"(b[1]) : "r"(addr));
                #pragma unroll
                for (int mt = 0; mt < 2; mt++) {
                    asm volatile(
                        "mma.sync.aligned.m16n8k16.row.col.f32.f16.f16.f32 "
                        "{%0,%1,%2,%3},{%4,%5,%6,%7},{%8,%9},{%0,%1,%2,%3};"
                        : "+f"(acc[mt][nt][0]), "+f"(acc[mt][nt][1]),
                          "+f"(acc[mt][nt][2]), "+f"(acc[mt][nt][3])
                        : "r"(a[mt][0]), "r"(a[mt][1]), "r"(a[mt][2]), "r"(a[mt][3]),
                          "r"(b[0]), "r"(b[1]));
                }
            }
        }
    }

    // epilogue: fp16 store
    #pragma unroll
    for (int mt = 0; mt < 2; mt++) {
        #pragma unroll
        for (int nt = 0; nt < 8; nt++) {
            int row = m0 + wm + mt * 16 + g;
            int col = wn + nt * 8 + tg * 2;
            if (row < NN)
                g_xw1h[(size_t)row * 64 + (col >> 1)] =
                    __floats2half2_rn(acc[mt][nt][0], acc[mt][nt][1]);
            if (row + 8 < NN)
                g_xw1h[(size_t)(row + 8) * 64 + (col >> 1)] =
                    __floats2half2_rn(acc[mt][nt][2], acc[mt][nt][3]);
        }
    }
}

// ---------------------- prop1 + bias + relu + GEMM2 fused, persistent warps
__device__ __forceinline__ float4 ld_xw1_row4(int node, int lane) {
    uint2 raw = *reinterpret_cast<const uint2*>(g_xw1h + (size_t)node * 64 + lane * 2);
    __half2 a0 = *reinterpret_cast<__half2*>(&raw.x);
    __half2 a1 = *reinterpret_cast<__half2*>(&raw.y);
    float2 f0 = __half22float2(a0);
    float2 f1 = __half22float2(a1);
    return make_float4(f0.x, f0.y, f1.x, f1.y);
}

__global__ void __launch_bounds__(256) k_prop1g2(const float* __restrict__ b1,
                                                 const float* __restrict__ W2) {
    int lane   = threadIdx.x & 31;
    int warpId = blockIdx.x * 8 + (threadIdx.x >> 5);

    // W2 rows lane*4..lane*4+3 (16 classes each) pinned in registers
    float4 w2r[16];
    #pragma unroll
    for (int rr = 0; rr < 4; rr++)
        #pragma unroll
        for (int c4 = 0; c4 < 4; c4++)
            w2r[rr * 4 + c4] = *(const float4*)(W2 + (size_t)(lane * 4 + rr) * NC + c4 * 4);
    float4 bia = *(const float4*)(b1 + lane * 4);

    for (int node = warpId; node < NN; node += P1_WARPS) {
        float dv  = g_dinv[node];
        float slw = dv * dv;
        float4 a = ld_xw1_row4(node, lane);
        float4 acc = make_float4(a.x * slw, a.y * slw, a.z * slw, a.w * slw);

        int s = g_start[node], e = g_start[node + 1];
        int i = s;
        for (; i + 2 <= e; i += 2) {
            unsigned long long e0 = __ldg(&g_edge[i]);
            unsigned long long e1 = __ldg(&g_edge[i + 1]);
            int   s0 = (int)(e0 >> 32);
            int   s1 = (int)(e1 >> 32);
            float w0 = __uint_as_float((unsigned)e0);
            float w1 = __uint_as_float((unsigned)e1);
            float4 v0 = ld_xw1_row4(s0, lane);
            float4 v1 = ld_xw1_row4(s1, lane);
            acc.x = fmaf(w0, v0.x, fmaf(w1, v1.x, acc.x));
            acc.y = fmaf(w0, v0.y, fmaf(w1, v1.y, acc.y));
            acc.z = fmaf(w0, v0.z, fmaf(w1, v1.z, acc.z));
            acc.w = fmaf(w0, v0.w, fmaf(w1, v1.w, acc.w));
        }
        if (i < e) {
            unsigned long long e0 = __ldg(&g_edge[i]);
            int   s0 = (int)(e0 >> 32);
            float w0 = __uint_as_float((unsigned)e0);
            float4 v0 = ld_xw1_row4(s0, lane);
            acc.x = fmaf(w0, v0.x, acc.x);
            acc.y = fmaf(w0, v0.y, acc.y);
            acc.z = fmaf(w0, v0.z, acc.z);
            acc.w = fmaf(w0, v0.w, acc.w);
        }

        float4 r;
        r.x = fmaxf(acc.x + bia.x, 0.0f);
        r.y = fmaxf(acc.y + bia.y, 0.0f);
        r.z = fmaxf(acc.z + bia.z, 0.0f);
        r.w = fmaxf(acc.w + bia.w, 0.0f);

        // per-lane partial logits: p[c] = sum_j r[j] * W2[lane*4+j][c]
        float p[16];
        #pragma unroll
        for (int c4 = 0; c4 < 4; c4++) {
            float4 q0 = w2r[0 * 4 + c4];
            float4 q1 = w2r[1 * 4 + c4];
            float4 q2 = w2r[2 * 4 + c4];
            float4 q3 = w2r[3 * 4 + c4];
            p[c4 * 4 + 0] = fmaf(r.x, q0.x, fmaf(r.y, q1.x, fmaf(r.z, q2.x, r.w * q3.x)));
            p[c4 * 4 + 1] = fmaf(r.x, q0.y, fmaf(r.y, q1.y, fmaf(r.z, q2.y, r.w * q3.y)));
            p[c4 * 4 + 2] = fmaf(r.x, q0.z, fmaf(r.y, q1.z, fmaf(r.z, q2.z, r.w * q3.z)));
            p[c4 * 4 + 3] = fmaf(r.x, q0.w, fmaf(r.y, q1.w, fmaf(r.z, q2.w, r.w * q3.w)));
        }
        float outv = 0.0f;
        #pragma unroll
        for (int c = 0; c < 16; c++) {
            float sv = p[c];
            sv += __shfl_xor_sync(0xffffffffu, sv, 16);
            sv += __shfl_xor_sync(0xffffffffu, sv, 8);
            sv += __shfl_xor_sync(0xffffffffu, sv, 4);
            sv += __shfl_xor_sync(0xffffffffu, sv, 2);
            sv += __shfl_xor_sync(0xffffffffu, sv, 1);
            if (lane == c) outv = sv;
        }
        if (lane < 16) g_hw2[(size_t)node * NC + lane] = outv;
    }
}

// -------------------- prop2 + b2 + log_softmax fused
__global__ void __launch_bounds__(256) k_prop2(const float* __restrict__ b2,
                                               float* __restrict__ out) {
    int node = blockIdx.x * (blockDim.x >> 5) + (threadIdx.x >> 5);
    if (node >= NN) return;
    int lane = threadIdx.x & 31;
    int half = lane >> 4;
    int cls  = lane & 15;

    float dv  = g_dinv[node];
    float acc = (half == 0) ? g_hw2[(size_t)node * NC + cls] * dv * dv : 0.0f;

    int s = g_start[node], e = g_start[node + 1];
    for (int i = s + half; i < e; i += 2) {
        unsigned long long ed = __ldg(&g_edge[i]);
        int   src = (int)(ed >> 32);
        float w   = __uint_as_float((unsigned)ed);
        acc = fmaf(w, __ldg(&g_hw2[(size_t)src * NC + cls]), acc);
    }
    acc += __shfl_xor_sync(0xffffffffu, acc, 16);

    float v = acc + b2[cls];
    float m = v;
    #pragma unroll
    for (int off = 8; off; off >>= 1) m = fmaxf(m, __shfl_xor_sync(0xffffffffu, m, off));
    float ex  = expf(v - m);
    float sum = ex;
    #pragma unroll
    for (int off = 8; off; off >>= 1) sum += __shfl_xor_sync(0xffffffffu, sum, off);
    float res = v - m - logf(sum);
    if (lane < 16) out[(size_t)node * NC + lane] = res;
}

// ---------------------------------------------------------------- launcher
extern "C" void kernel_launch(void* const* d_in, const int* in_sizes, int n_in,
                              void* d_out, int out_size) {
    const float* features = (const float*)d_in[0];
    const int*   ei       = (const int*)d_in[1];
    const float* ew       = (const float*)d_in[2];
    const float* W1       = (const float*)d_in[3];
    const float* b1       = (const float*)d_in[4];
    const float* W2       = (const float*)d_in[5];
    const float* b2       = (const float*)d_in[6];
    float* out = (float*)d_out;

    k_init   <<<(NN + 255) / 256, 256>>>();
    k_deg    <<<(EE + 255) / 256, 256>>>(ei, ew);
    k_scan1  <<<SCAN_NBLK, 1024>>>();
    k_scan2  <<<1, 128>>>();
    k_scan3  <<<SCAN_NBLK, 1024>>>();
    k_scatter<<<(EE + 255) / 256, 256>>>(ei, ew);

    k_gemm1  <<<(NN + 127) / 128, 256>>>(features, W1);
    k_prop1g2<<<P1_WARPS / 8, 256>>>(b1, W2);
    k_prop2  <<<(NN + 7) / 8, 256>>>(b2, out);
}

// round 5
// speedup vs baseline: 2.3140x; 2.3140x over previous
#include <cuda_runtime.h>
#include <cuda_fp16.h>
#include <math.h>

#define NN 100000
#define EE 3200000
#define NF 256
#define NH 128
#define NC 16
#define SCAN_NBLK ((NN + 1023) / 1024)

// ---- static device scratch ----
__device__ unsigned long long g_degcnt[NN];   // hi32: count, lo32: deg*2^20
__device__ float   g_dinv[NN];
__device__ int     g_start[NN + 1];
__device__ int     g_cursor[NN];
__device__ int     g_bsum[256];
__device__ unsigned long long g_edge[EE];     // hi32: src, lo32: float bits of norm
__device__ __half2 g_xw1h[(size_t)NN * (NH / 2)];
__device__ float   g_h[(size_t)NN * NH];
__device__ float   g_hw2[(size_t)NN * NC];

// ---------------------------------------------------------------- init
__global__ void k_init() {
    int i = blockIdx.x * blockDim.x + threadIdx.x;
    if (i < NN) g_degcnt[i] = (1ULL << 20);   // deg=1.0 (self-loop), cnt=0
}

// ------------------------------------------ degree + count (one packed atomic)
__global__ void k_deg(const int* __restrict__ ei, const float* __restrict__ ew) {
    int e = blockIdx.x * blockDim.x + threadIdx.x;
    if (e < EE) {
        int c = ei[EE + e];
        unsigned fw = (unsigned)__float2uint_rn(ew[e] * 1048576.0f);
        atomicAdd(&g_degcnt[c], (1ULL << 32) | (unsigned long long)fw);
    }
}

// ------------------------------------------ 3-phase scan (+ dinv in phase 1)
__global__ void __launch_bounds__(1024) k_scan1() {
    __shared__ int wsum[32];
    int t = threadIdx.x, lane = t & 31, warp = t >> 5;
    int i = blockIdx.x * 1024 + t;
    int v = 0;
    if (i < NN) {
        unsigned long long pk = g_degcnt[i];
        v = (int)(pk >> 32);
        float deg = (float)(unsigned)(pk & 0xffffffffULL) * (1.0f / 1048576.0f);
        g_dinv[i] = rsqrtf(deg);              // deg >= 1 always
    }
    int x = v;
    #pragma unroll
    for (int off = 1; off < 32; off <<= 1) {
        int y = __shfl_up_sync(0xffffffffu, x, off);
        if (lane >= off) x += y;
    }
    if (lane == 31) wsum[warp] = x;
    __syncthreads();
    if (warp == 0) {
        int s = wsum[lane];
        #pragma unroll
        for (int off = 1; off < 32; off <<= 1) {
            int y = __shfl_up_sync(0xffffffffu, s, off);
            if (lane >= off) s += y;
        }
        wsum[lane] = s;
    }
    __syncthreads();
    int incl = x + (warp > 0 ? wsum[warp - 1] : 0);
    if (i < NN) g_start[i] = incl - v;
    if (t == 1023) g_bsum[blockIdx.x] = incl;
}

__global__ void k_scan2() {
    int t = threadIdx.x, lane = t & 31, warp = t >> 5;
    __shared__ int wsum[4];
    int v = (t < SCAN_NBLK) ? g_bsum[t] : 0;
    int x = v;
    #pragma unroll
    for (int off = 1; off < 32; off <<= 1) {
        int y = __shfl_up_sync(0xffffffffu, x, off);
        if (lane >= off) x += y;
    }
    if (lane == 31) wsum[warp] = x;
    __syncthreads();
    int woff = 0;
    for (int w = 0; w < warp; w++) woff += wsum[w];
    int incl = x + woff;
    if (t < SCAN_NBLK) g_bsum[t] = incl - v;
    if (t == SCAN_NBLK - 1) g_start[NN] = incl;
}

__global__ void __launch_bounds__(1024) k_scan3() {
    int i = blockIdx.x * 1024 + threadIdx.x;
    if (i < NN) {
        int s = g_start[i] + g_bsum[blockIdx.x];
        g_start[i]  = s;
        g_cursor[i] = s;
    }
}

// ------------------------------------- scatter edges into CSC, packed records
__global__ void k_scatter(const int* __restrict__ ei, const float* __restrict__ ew) {
    int e = blockIdx.x * blockDim.x + threadIdx.x;
    if (e < EE) {
        int r = ei[e];
        int c = ei[EE + e];
        float nrm = g_dinv[r] * ew[e] * g_dinv[c];
        int pos = atomicAdd(&g_cursor[c], 1);
        g_edge[pos] = ((unsigned long long)(unsigned)r << 32)
                    | (unsigned long long)__float_as_uint(nrm);
    }
}

// ------------------------------------------------------------- GEMM1: X@W1
// HMMA, A fragments direct-from-gmem (registers, MLP=32), B fp16 in smem.
// 8 warps x 16 rows = 128 rows/block; each warp spans all 128 N.
__global__ void __launch_bounds__(256) k_gemm1(const float* __restrict__ A,
                                               const float* __restrict__ B) {
    __shared__ __half sB[128 * 136];   // one 128-K chunk of B, +8 halves pad

    const int tid  = threadIdx.x;
    const int lane = tid & 31;
    const int w    = tid >> 5;
    const int m0   = blockIdx.x * 128;
    const int warpRow = m0 + w * 16;
    const int g    = lane >> 2;
    const int tg   = lane & 3;

    float acc[16][4];
    #pragma unroll
    for (int nt = 0; nt < 16; nt++)
        #pragma unroll
        for (int j = 0; j < 4; j++) acc[nt][j] = 0.0f;

    const int r0 = warpRow + g;
    const int r1 = r0 + 8;
    const bool v0 = r0 < NN, v1 = r1 < NN;

    for (int kc = 0; kc < 2; kc++) {
        const int kbase = kc * 128;
        __syncthreads();
        // convert B chunk [128k x 128n] fp32 -> fp16 smem
        #pragma unroll
        for (int l = 0; l < 16; l++) {
            int f4 = tid + l * 256;          // 0..4095
            int kr = f4 >> 5;
            int c4 = f4 & 31;
            float4 v = *(const float4*)(B + (size_t)(kbase + kr) * NH + c4 * 4);
            __half2 h0 = __floats2half2_rn(v.x, v.y);
            __half2 h1 = __floats2half2_rn(v.z, v.w);
            uint2 pk;
            pk.x = *(unsigned*)&h0; pk.y = *(unsigned*)&h1;
            *(uint2*)&sB[kr * 136 + c4 * 4] = pk;
        }
        __syncthreads();

        // prefetch ALL A fragments for this chunk (32 float2 loads, MLP=32)
        unsigned ah[8][4];
        {
            const float* A0 = A + (size_t)(v0 ? r0 : 0) * NF + kbase + tg * 2;
            const float* A1 = A + (size_t)(v1 ? r1 : 0) * NF + kbase + tg * 2;
            #pragma unroll
            for (int s = 0; s < 8; s++) {
                float2 f0 = v0 ? *(const float2*)(A0 + s * 16)     : make_float2(0.f, 0.f);
                float2 f1 = v1 ? *(const float2*)(A1 + s * 16)     : make_float2(0.f, 0.f);
                float2 f2 = v0 ? *(const float2*)(A0 + s * 16 + 8) : make_float2(0.f, 0.f);
                float2 f3 = v1 ? *(const float2*)(A1 + s * 16 + 8) : make_float2(0.f, 0.f);
                __half2 h;
                h = __floats2half2_rn(f0.x, f0.y); ah[s][0] = *(unsigned*)&h;
                h = __floats2half2_rn(f1.x, f1.y); ah[s][1] = *(unsigned*)&h;
                h = __floats2half2_rn(f2.x, f2.y); ah[s][2] = *(unsigned*)&h;
                h = __floats2half2_rn(f3.x, f3.y); ah[s][3] = *(unsigned*)&h;
            }
        }

        #pragma unroll
        for (int s = 0; s < 8; s++) {
            #pragma unroll
            for (int nt = 0; nt < 16; nt++) {
                unsigned b0, b1;
                unsigned addr = (unsigned)__cvta_generic_to_shared(
                    &sB[(s * 16 + (lane & 15)) * 136 + nt * 8]);
                asm volatile("ldmatrix.sync.aligned.m8n8.x2.trans.shared.b16 {%0,%1},[%2];"
                             : "=r"(b0), "=r"(b1) : "r"(addr));
                asm volatile(
                    "mma.sync.aligned.m16n8k16.row.col.f32.f16.f16.f32 "
                    "{%0,%1,%2,%3},{%4,%5,%6,%7},{%8,%9},{%0,%1,%2,%3};"
                    : "+f"(acc[nt][0]), "+f"(acc[nt][1]),
                      "+f"(acc[nt][2]), "+f"(acc[nt][3])
                    : "r"(ah[s][0]), "r"(ah[s][1]), "r"(ah[s][2]), "r"(ah[s][3]),
                      "r"(b0), "r"(b1));
            }
        }
    }

    // epilogue: fp16 store. lane holds (r0, nt*8+tg*2,+1) and (r1, same cols)
    #pragma unroll
    for (int nt = 0; nt < 16; nt++) {
        int col = nt * 8 + tg * 2;
        if (v0)
            g_xw1h[(size_t)r0 * 64 + (col >> 1)] = __floats2half2_rn(acc[nt][0], acc[nt][1]);
        if (v1)
            g_xw1h[(size_t)r1 * 64 + (col >> 1)] = __floats2half2_rn(acc[nt][2], acc[nt][3]);
    }
}

// ------------------------------------------- prop1: h = relu(A_norm @ xw1 + b1)
// one warp per node, 4 feats (one 8-byte half2x2) per lane.  (R2-proven)
__device__ __forceinline__ float4 ld_xw1_row4(int node, int lane) {
    uint2 raw = *reinterpret_cast<const uint2*>(g_xw1h + (size_t)node * 64 + lane * 2);
    __half2 a0 = *reinterpret_cast<__half2*>(&raw.x);
    __half2 a1 = *reinterpret_cast<__half2*>(&raw.y);
    float2 f0 = __half22float2(a0);
    float2 f1 = __half22float2(a1);
    return make_float4(f0.x, f0.y, f1.x, f1.y);
}

__global__ void __launch_bounds__(256) k_prop1(const float* __restrict__ b1) {
    int node = blockIdx.x * (blockDim.x >> 5) + (threadIdx.x >> 5);
    if (node >= NN) return;
    int lane = threadIdx.x & 31;

    float dv  = g_dinv[node];
    float slw = dv * dv;
    float4 a = ld_xw1_row4(node, lane);
    float4 acc = make_float4(a.x * slw, a.y * slw, a.z * slw, a.w * slw);

    int s = g_start[node], e = g_start[node + 1];
    int i = s;
    for (; i + 2 <= e; i += 2) {
        unsigned long long e0 = __ldg(&g_edge[i]);
        unsigned long long e1 = __ldg(&g_edge[i + 1]);
        int   s0 = (int)(e0 >> 32);
        int   s1 = (int)(e1 >> 32);
        float w0 = __uint_as_float((unsigned)e0);
        float w1 = __uint_as_float((unsigned)e1);
        float4 q0 = ld_xw1_row4(s0, lane);
        float4 q1 = ld_xw1_row4(s1, lane);
        acc.x = fmaf(w0, q0.x, fmaf(w1, q1.x, acc.x));
        acc.y = fmaf(w0, q0.y, fmaf(w1, q1.y, acc.y));
        acc.z = fmaf(w0, q0.z, fmaf(w1, q1.z, acc.z));
        acc.w = fmaf(w0, q0.w, fmaf(w1, q1.w, acc.w));
    }
    if (i < e) {
        unsigned long long e0 = __ldg(&g_edge[i]);
        int   s0 = (int)(e0 >> 32);
        float w0 = __uint_as_float((unsigned)e0);
        float4 q0 = ld_xw1_row4(s0, lane);
        acc.x = fmaf(w0, q0.x, acc.x);
        acc.y = fmaf(w0, q0.y, acc.y);
        acc.z = fmaf(w0, q0.z, acc.z);
        acc.w = fmaf(w0, q0.w, acc.w);
    }

    float4 b = *(const float4*)(b1 + lane * 4);
    float4 r;
    r.x = fmaxf(acc.x + b.x, 0.0f);
    r.y = fmaxf(acc.y + b.y, 0.0f);
    r.z = fmaxf(acc.z + b.z, 0.0f);
    r.w = fmaxf(acc.w + b.w, 0.0f);
    *(float4*)(g_h + (size_t)node * NH + lane * 4) = r;
}

// ------------------------------------------------------------- GEMM2: h@W2 (R2-proven)
__global__ void __launch_bounds__(256) k_gemm2(const float* __restrict__ W2) {
    __shared__ float sh[64 * 132];
    __shared__ float sw[128 * 16];
    int tid = threadIdx.x;
    int n0  = blockIdx.x * 64;

    #pragma unroll
    for (int l = 0; l < 2; l++) {
        int idx = tid + l * 256;
        *(((float4*)sw) + idx) = *(((const float4*)W2) + idx);
    }
    #pragma unroll
    for (int l = 0; l < 8; l++) {
        int f4 = tid + l * 256;
        int r  = f4 >> 5;
        int c4 = f4 & 31;
        int gn = n0 + r;
        float4 v = (gn < NN) ? *(const float4*)(g_h + (size_t)gn * NH + c4 * 4)
                             : make_float4(0.f, 0.f, 0.f, 0.f);
        *(float4*)(sh + r * 132 + c4 * 4) = v;
    }
    __syncthreads();

    int nl = tid >> 2;
    int cg = tid & 3;
    float4 acc = make_float4(0.f, 0.f, 0.f, 0.f);
    const float* hrow = sh + nl * 132;
    #pragma unroll
    for (int k = 0; k < 128; k++) {
        float hv = hrow[k];
        float4 wv = *(((const float4*)(sw + k * 16)) + cg);
        acc.x = fmaf(hv, wv.x, acc.x);
        acc.y = fmaf(hv, wv.y, acc.y);
        acc.z = fmaf(hv, wv.z, acc.z);
        acc.w = fmaf(hv, wv.w, acc.w);
    }
    int gn = n0 + nl;
    if (gn < NN) *(float4*)(g_hw2 + (size_t)gn * NC + cg * 4) = acc;
}

// -------------------- prop2 + b2 + log_softmax fused (R2-proven, packed edges)
__global__ void __launch_bounds__(256) k_prop2(const float* __restrict__ b2,
                                               float* __restrict__ out) {
    int node = blockIdx.x * (blockDim.x >> 5) + (threadIdx.x >> 5);
    if (node >= NN) return;
    int lane = threadIdx.x & 31;
    int half = lane >> 4;
    int cls  = lane & 15;

    float dv  = g_dinv[node];
    float acc = (half == 0) ? g_hw2[(size_t)node * NC + cls] * dv * dv : 0.0f;

    int s = g_start[node], e = g_start[node + 1];
    for (int i = s + half; i < e; i += 2) {
        unsigned long long ed = __ldg(&g_edge[i]);
        int   src = (int)(ed >> 32);
        float w   = __uint_as_float((unsigned)ed);
        acc = fmaf(w, __ldg(&g_hw2[(size_t)src * NC + cls]), acc);
    }
    acc += __shfl_xor_sync(0xffffffffu, acc, 16);

    float v = acc + b2[cls];
    float m = v;
    #pragma unroll
    for (int off = 8; off; off >>= 1) m = fmaxf(m, __shfl_xor_sync(0xffffffffu, m, off));
    float ex  = expf(v - m);
    float sum = ex;
    #pragma unroll
    for (int off = 8; off; off >>= 1) sum += __shfl_xor_sync(0xffffffffu, sum, off);
    float res = v - m - logf(sum);
    if (lane < 16) out[(size_t)node * NC + lane] = res;
}

// ---------------------------------------------------------------- launcher
extern "C" void kernel_launch(void* const* d_in, const int* in_sizes, int n_in,
                              void* d_out, int out_size) {
    const float* features = (const float*)d_in[0];
    const int*   ei       = (const int*)d_in[1];
    const float* ew       = (const float*)d_in[2];
    const float* W1       = (const float*)d_in[3];
    const float* b1       = (const float*)d_in[4];
    const float* W2       = (const float*)d_in[5];
    const float* b2       = (const float*)d_in[6];
    float* out = (float*)d_out;

    k_init   <<<(NN + 255) / 256, 256>>>();
    k_deg    <<<(EE + 255) / 256, 256>>>(ei, ew);
    k_scan1  <<<SCAN_NBLK, 1024>>>();
    k_scan2  <<<1, 128>>>();
    k_scan3  <<<SCAN_NBLK, 1024>>>();
    k_scatter<<<(EE + 255) / 256, 256>>>(ei, ew);

    k_gemm1  <<<(NN + 127) / 128, 256>>>(features, W1);
    k_prop1  <<<(NN + 7) / 8, 256>>>(b1);
    k_gemm2  <<<(NN + 63) / 64, 256>>>(W2);
    k_prop2  <<<(NN + 7) / 8, 256>>>(b2, out);
}